// round 6
// baseline (speedup 1.0000x reference)
#include <cuda_runtime.h>

#define KTOT   1000000
#define NCOLS  70400
#define SENT   -9999999.0f

typedef unsigned long long u64;

// All weights/biases live in constant memory: warp-uniform access -> LDCU
// (uniform port), completely off the L1/shared pipe.
__constant__ ulonglong2 cW1v[18];    // W1: 72 floats  (row = 1 ulonglong2)
__constant__ u64        cW2v[324];   // W2: 648 floats (row = 9 u64)
__constant__ ulonglong2 cW3v[324];   // W3: 1296 floats (row = 9 ulonglong2)
__constant__ u64        cW4v[18];    // W4: 36 floats
__constant__ float      cb1f[18], cb2f[36], cb3f[36], cb4f[1];

static __device__ __forceinline__ u64 pack2(float lo, float hi) {
    u64 r; asm("mov.b64 %0,{%1,%2};" : "=l"(r) : "f"(lo), "f"(hi)); return r;
}
static __device__ __forceinline__ void unpack2(u64 v, float& lo, float& hi) {
    asm("mov.b64 {%0,%1},%2;" : "=f"(lo), "=f"(hi) : "l"(v));
}
static __device__ __forceinline__ u64 fma2(u64 a, u64 b, u64 c) {
    u64 d; asm("fma.rn.f32x2 %0,%1,%2,%3;" : "=l"(d) : "l"(a), "l"(b), "l"(c)); return d;
}
// horizontal add of the two f32 lanes (bias pre-folded into lane 0)
static __device__ __forceinline__ float hadd(u64 v) {
    float lo, hi; unpack2(v, lo, hi);
    return lo + hi;
}
// float atomic max via sign-split integer atomics (no return -> REDG)
static __device__ __forceinline__ void atomicMaxF(float* a, float v) {
    if (v >= 0.0f) atomicMax((int*)a, __float_as_int(v));
    else           atomicMin((unsigned int*)a, __float_as_uint(v));
}

__global__ void init_out_kernel(float* out, int n) {
    int i = blockIdx.x * blockDim.x + threadIdx.x;
    if (i < n) out[i] = (i < NCOLS) ? SENT : 1.0f;   // trailing element(s) = flag
}

__global__ __launch_bounds__(128) void mlp_scatter_kernel(
    const float* __restrict__ x,        // (4, K) row-major
    const int* __restrict__ tix,        // (K, 2) int32, col index at [2k+1]
    float* __restrict__ out)
{
    const int t = threadIdx.x;
    const long long k0 = 4LL * ((long long)blockIdx.x * 128 + t);
    if (k0 >= KTOT) return;

    // Load 4 columns of the (4,K) input; k-pack per column along the i-dim.
    float4 r0 = *reinterpret_cast<const float4*>(x + 0 * (size_t)KTOT + k0);
    float4 r1 = *reinterpret_cast<const float4*>(x + 1 * (size_t)KTOT + k0);
    float4 r2 = *reinterpret_cast<const float4*>(x + 2 * (size_t)KTOT + k0);
    float4 r3 = *reinterpret_cast<const float4*>(x + 3 * (size_t)KTOT + k0);
    u64 xv[4][2];
    xv[0][0] = pack2(r0.x, r1.x); xv[0][1] = pack2(r2.x, r3.x);
    xv[1][0] = pack2(r0.y, r1.y); xv[1][1] = pack2(r2.y, r3.y);
    xv[2][0] = pack2(r0.z, r1.z); xv[2][1] = pack2(r2.z, r3.z);
    xv[3][0] = pack2(r0.w, r1.w); xv[3][1] = pack2(r2.w, r3.w);

    // ---- Layer 1: 4 -> 18, outputs packed in pairs: h1[c][j/2] ----
    u64 h1[4][9];
    #pragma unroll
    for (int j = 0; j < 18; j += 2) {
        float ho[2][4];
        #pragma unroll
        for (int s = 0; s < 2; s++) {
            const int jj = j + s;
            ulonglong2 w = cW1v[jj];
            u64 bb = pack2(cb1f[jj], 0.0f);
            #pragma unroll
            for (int c = 0; c < 4; c++) {
                u64 a = fma2(w.x, xv[c][0], bb);
                a = fma2(w.y, xv[c][1], a);
                ho[s][c] = fmaxf(hadd(a), 0.0f);
            }
        }
        #pragma unroll
        for (int c = 0; c < 4; c++) h1[c][j / 2] = pack2(ho[0][c], ho[1][c]);
    }

    // ---- Layer 2: 18 -> 36, outputs packed: h2[c][j/2] ----
    u64 h2[4][18];
    #pragma unroll 4
    for (int j = 0; j < 36; j += 2) {
        float ho[2][4];
        #pragma unroll
        for (int s = 0; s < 2; s++) {
            const int jj = j + s;
            u64 bb = pack2(cb2f[jj], 0.0f);
            u64 a0 = bb, a1 = bb, a2 = bb, a3 = bb;
            #pragma unroll
            for (int i = 0; i < 9; i++) {
                u64 w = cW2v[jj * 9 + i];
                a0 = fma2(w, h1[0][i], a0);
                a1 = fma2(w, h1[1][i], a1);
                a2 = fma2(w, h1[2][i], a2);
                a3 = fma2(w, h1[3][i], a3);
            }
            ho[s][0] = fmaxf(hadd(a0), 0.0f);
            ho[s][1] = fmaxf(hadd(a1), 0.0f);
            ho[s][2] = fmaxf(hadd(a2), 0.0f);
            ho[s][3] = fmaxf(hadd(a3), 0.0f);
        }
        #pragma unroll
        for (int c = 0; c < 4; c++) h2[c][j / 2] = pack2(ho[0][c], ho[1][c]);
    }

    // ---- Layers 3+4 fused: 36 -> 36 -> 1 (h3 never stored) ----
    u64 vacc[4];
    vacc[0] = pack2(cb4f[0], 0.0f);
    vacc[1] = pack2(cb4f[0], 0.0f);
    vacc[2] = pack2(cb4f[0], 0.0f);
    vacc[3] = pack2(cb4f[0], 0.0f);
    // vacc carries (b4 + sum_even, sum_odd) per column... bias added once:
    vacc[1] = vacc[0]; vacc[2] = vacc[0]; vacc[3] = vacc[0];

    #pragma unroll 4
    for (int j = 0; j < 36; j += 2) {
        float ho[2][4];
        #pragma unroll
        for (int s = 0; s < 2; s++) {
            const int jj = j + s;
            u64 bb = pack2(cb3f[jj], 0.0f);
            u64 a0 = bb, a1 = bb, a2 = bb, a3 = bb;
            #pragma unroll
            for (int q = 0; q < 9; q++) {
                ulonglong2 w = cW3v[jj * 9 + q];
                a0 = fma2(w.x, h2[0][2 * q], a0);
                a1 = fma2(w.x, h2[1][2 * q], a1);
                a2 = fma2(w.x, h2[2][2 * q], a2);
                a3 = fma2(w.x, h2[3][2 * q], a3);
                a0 = fma2(w.y, h2[0][2 * q + 1], a0);
                a1 = fma2(w.y, h2[1][2 * q + 1], a1);
                a2 = fma2(w.y, h2[2][2 * q + 1], a2);
                a3 = fma2(w.y, h2[3][2 * q + 1], a3);
            }
            ho[s][0] = fmaxf(hadd(a0), 0.0f);
            ho[s][1] = fmaxf(hadd(a1), 0.0f);
            ho[s][2] = fmaxf(hadd(a2), 0.0f);
            ho[s][3] = fmaxf(hadd(a3), 0.0f);
        }
        u64 w4 = cW4v[j / 2];
        #pragma unroll
        for (int c = 0; c < 4; c++)
            vacc[c] = fma2(w4, pack2(ho[0][c], ho[1][c]), vacc[c]);
    }

    float v0 = hadd(vacc[0]), v1 = hadd(vacc[1]);
    float v2 = hadd(vacc[2]), v3 = hadd(vacc[3]);

    // (K,2) int32 pairs: column index at odd positions
    const int4 p01 = *reinterpret_cast<const int4*>(tix + 2 * k0);
    const int4 p23 = *reinterpret_cast<const int4*>(tix + 2 * k0 + 4);
    if ((unsigned)p01.y < NCOLS) atomicMaxF(out + p01.y, v0);
    if ((unsigned)p01.w < NCOLS) atomicMaxF(out + p01.w, v1);
    if ((unsigned)p23.y < NCOLS) atomicMaxF(out + p23.y, v2);
    if ((unsigned)p23.w < NCOLS) atomicMaxF(out + p23.w, v3);
}

extern "C" void kernel_launch(void* const* d_in, const int* in_sizes, int n_in,
                              void* d_out, int out_size) {
    const float* x   = (const float*)d_in[0];
    const int*   tix = (const int*)d_in[1];
    float* out = (float*)d_out;

    // Stage weights into constant memory (async D2D copies -> memcpy nodes,
    // graph-capturable; no allocation).
    cudaMemcpyToSymbolAsync(cW1v, d_in[2],   72 * 4, 0, cudaMemcpyDeviceToDevice);
    cudaMemcpyToSymbolAsync(cb1f, d_in[3],   18 * 4, 0, cudaMemcpyDeviceToDevice);
    cudaMemcpyToSymbolAsync(cW2v, d_in[4],  648 * 4, 0, cudaMemcpyDeviceToDevice);
    cudaMemcpyToSymbolAsync(cb2f, d_in[5],   36 * 4, 0, cudaMemcpyDeviceToDevice);
    cudaMemcpyToSymbolAsync(cW3v, d_in[6], 1296 * 4, 0, cudaMemcpyDeviceToDevice);
    cudaMemcpyToSymbolAsync(cb3f, d_in[7],   36 * 4, 0, cudaMemcpyDeviceToDevice);
    cudaMemcpyToSymbolAsync(cW4v, d_in[8],   36 * 4, 0, cudaMemcpyDeviceToDevice);
    cudaMemcpyToSymbolAsync(cb4f, d_in[9],    1 * 4, 0, cudaMemcpyDeviceToDevice);

    init_out_kernel<<<(out_size + 255) / 256, 256>>>(out, out_size);

    const int nthreads = KTOT / 4;                 // 4 columns per thread
    mlp_scatter_kernel<<<(nthreads + 127) / 128, 128>>>(x, tix, out);
}

// round 7
// speedup vs baseline: 1.2331x; 1.2331x over previous
#include <cuda_runtime.h>

#define KTOT   1000000
#define NCOLS  70400
#define SENT   -9999999.0f

typedef unsigned long long u64;

// Big layer (W3) + W4/b3/b4 on the constant port (LDC), W1/W2 in shared (LDS):
// weight traffic split across two independent ports.
__constant__ ulonglong2 cW3v[324];   // W3: 1296 floats, row = 9 ulonglong2
__constant__ u64        cW4v[18];    // W4: 36 floats
__constant__ float      cb3f[36], cb4f[1];

static __device__ __forceinline__ u64 pack2(float lo, float hi) {
    u64 r; asm("mov.b64 %0,{%1,%2};" : "=l"(r) : "f"(lo), "f"(hi)); return r;
}
static __device__ __forceinline__ void unpack2(u64 v, float& lo, float& hi) {
    asm("mov.b64 {%0,%1},%2;" : "=f"(lo), "=f"(hi) : "l"(v));
}
static __device__ __forceinline__ u64 fma2(u64 a, u64 b, u64 c) {
    u64 d; asm("fma.rn.f32x2 %0,%1,%2,%3;" : "=l"(d) : "l"(a), "l"(b), "l"(c)); return d;
}
// horizontal add of the two f32 lanes (bias pre-folded into lane 0)
static __device__ __forceinline__ float hadd(u64 v) {
    float lo, hi; unpack2(v, lo, hi);
    return lo + hi;
}
// float atomic max via sign-split integer atomics (no return -> REDG)
static __device__ __forceinline__ void atomicMaxF(float* a, float v) {
    if (v >= 0.0f) atomicMax((int*)a, __float_as_int(v));
    else           atomicMin((unsigned int*)a, __float_as_uint(v));
}

__global__ void init_out_kernel(float* out, int n) {
    int i = blockIdx.x * blockDim.x + threadIdx.x;
    if (i < n) out[i] = (i < NCOLS) ? SENT : 1.0f;   // trailing element(s) = flag
}

__global__ __launch_bounds__(128, 3) void mlp_scatter_kernel(
    const float* __restrict__ x,        // (4, K) row-major
    const int* __restrict__ tix,        // (K, 2) int32, col index at [2k+1]
    const float* __restrict__ W1, const float* __restrict__ b1,
    const float* __restrict__ W2, const float* __restrict__ b2,
    float* __restrict__ out)
{
    // W1: 18 rows x 4 w  = 1 ulonglong2/row ; W2: 36 rows x 18 w = 4 ulonglong2 + u64 tail
    __shared__ ulonglong2 sW1[18];
    __shared__ ulonglong2 sW2[144];
    __shared__ u64        sW2t[36];
    __shared__ u64 sb1[18], sb2[36];

    const int t = threadIdx.x;
    for (int i = t; i < 18;  i += 128) sW1[i] = ((const ulonglong2*)W1)[i];
    for (int i = t; i < 18;  i += 128) sb1[i] = pack2(b1[i], 0.0f);
    for (int i = t; i < 144; i += 128) {
        int row = i >> 2, q = i & 3;
        sW2[i] = make_ulonglong2(((const u64*)W2)[row * 9 + 2 * q],
                                 ((const u64*)W2)[row * 9 + 2 * q + 1]);
    }
    for (int i = t; i < 36;  i += 128) sW2t[i] = ((const u64*)W2)[i * 9 + 8];
    for (int i = t; i < 36;  i += 128) sb2[i] = pack2(b2[i], 0.0f);
    __syncthreads();

    const long long k0 = 2LL * ((long long)blockIdx.x * 128 + t);
    if (k0 >= KTOT) return;

    // Two adjacent columns; k-pack each column's 4 input features into 2 u64.
    float2 r0 = *reinterpret_cast<const float2*>(x + 0 * (size_t)KTOT + k0);
    float2 r1 = *reinterpret_cast<const float2*>(x + 1 * (size_t)KTOT + k0);
    float2 r2 = *reinterpret_cast<const float2*>(x + 2 * (size_t)KTOT + k0);
    float2 r3 = *reinterpret_cast<const float2*>(x + 3 * (size_t)KTOT + k0);
    u64 xv[2][2];
    xv[0][0] = pack2(r0.x, r1.x); xv[0][1] = pack2(r2.x, r3.x);
    xv[1][0] = pack2(r0.y, r1.y); xv[1][1] = pack2(r2.y, r3.y);

    // ---- Layer 1: 4 -> 18 (shared weights), outputs packed: h1[c][j/2] ----
    u64 h1[2][9];
    #pragma unroll
    for (int j = 0; j < 18; j += 2) {
        float ho[2][2];
        #pragma unroll
        for (int s = 0; s < 2; s++) {
            const int jj = j + s;
            ulonglong2 w = sW1[jj];
            u64 bb = sb1[jj];
            #pragma unroll
            for (int c = 0; c < 2; c++) {
                u64 a = fma2(w.x, xv[c][0], bb);
                a = fma2(w.y, xv[c][1], a);
                ho[s][c] = fmaxf(hadd(a), 0.0f);
            }
        }
        h1[0][j / 2] = pack2(ho[0][0], ho[1][0]);
        h1[1][j / 2] = pack2(ho[0][1], ho[1][1]);
    }

    // ---- Layer 2: 18 -> 36 (shared weights), outputs packed: h2[c][j/2] ----
    u64 h2[2][18];
    #pragma unroll 4
    for (int j = 0; j < 36; j += 2) {
        float ho[2][2];
        #pragma unroll
        for (int s = 0; s < 2; s++) {
            const int jj = j + s;
            u64 a0 = sb2[jj], a1 = sb2[jj];
            #pragma unroll
            for (int q = 0; q < 4; q++) {
                ulonglong2 w = sW2[jj * 4 + q];
                a0 = fma2(w.x, h1[0][2 * q], a0);
                a1 = fma2(w.x, h1[1][2 * q], a1);
                a0 = fma2(w.y, h1[0][2 * q + 1], a0);
                a1 = fma2(w.y, h1[1][2 * q + 1], a1);
            }
            u64 wt = sW2t[jj];
            a0 = fma2(wt, h1[0][8], a0);
            a1 = fma2(wt, h1[1][8], a1);
            ho[s][0] = fmaxf(hadd(a0), 0.0f);
            ho[s][1] = fmaxf(hadd(a1), 0.0f);
        }
        h2[0][j / 2] = pack2(ho[0][0], ho[1][0]);
        h2[1][j / 2] = pack2(ho[0][1], ho[1][1]);
    }

    // ---- Layers 3+4 fused (constant-port weights): 36 -> 36 -> 1 ----
    u64 vacc0 = pack2(cb4f[0], 0.0f), vacc1 = vacc0;
    #pragma unroll 4
    for (int j = 0; j < 36; j += 2) {
        float ho[2][2];
        #pragma unroll
        for (int s = 0; s < 2; s++) {
            const int jj = j + s;
            u64 bb = pack2(cb3f[jj], 0.0f);
            u64 a0 = bb, a1 = bb;
            #pragma unroll
            for (int q = 0; q < 9; q++) {
                ulonglong2 w = cW3v[jj * 9 + q];
                a0 = fma2(w.x, h2[0][2 * q], a0);
                a1 = fma2(w.x, h2[1][2 * q], a1);
                a0 = fma2(w.y, h2[0][2 * q + 1], a0);
                a1 = fma2(w.y, h2[1][2 * q + 1], a1);
            }
            ho[s][0] = fmaxf(hadd(a0), 0.0f);
            ho[s][1] = fmaxf(hadd(a1), 0.0f);
        }
        u64 w4 = cW4v[j / 2];
        vacc0 = fma2(w4, pack2(ho[0][0], ho[1][0]), vacc0);
        vacc1 = fma2(w4, pack2(ho[0][1], ho[1][1]), vacc1);
    }

    float v0 = hadd(vacc0);
    float v1 = hadd(vacc1);

    // (K,2) int32: one int4 covers both pairs; columns at .y/.w
    const int4 p = *reinterpret_cast<const int4*>(tix + 2 * k0);
    if ((unsigned)p.y < NCOLS) atomicMaxF(out + p.y, v0);
    if ((unsigned)p.w < NCOLS) atomicMaxF(out + p.w, v1);
}

extern "C" void kernel_launch(void* const* d_in, const int* in_sizes, int n_in,
                              void* d_out, int out_size) {
    const float* x   = (const float*)d_in[0];
    const int*   tix = (const int*)d_in[1];
    const float* W1 = (const float*)d_in[2];
    const float* b1 = (const float*)d_in[3];
    const float* W2 = (const float*)d_in[4];
    const float* b2 = (const float*)d_in[5];
    float* out = (float*)d_out;

    // Stage the big layer into constant memory (async D2D memcpy nodes).
    cudaMemcpyToSymbolAsync(cW3v, d_in[6], 1296 * 4, 0, cudaMemcpyDeviceToDevice);
    cudaMemcpyToSymbolAsync(cb3f, d_in[7],   36 * 4, 0, cudaMemcpyDeviceToDevice);
    cudaMemcpyToSymbolAsync(cW4v, d_in[8],   36 * 4, 0, cudaMemcpyDeviceToDevice);
    cudaMemcpyToSymbolAsync(cb4f, d_in[9],    1 * 4, 0, cudaMemcpyDeviceToDevice);

    init_out_kernel<<<(out_size + 255) / 256, 256>>>(out, out_size);

    const int nthreads = KTOT / 2;                 // 2 columns per thread
    mlp_scatter_kernel<<<(nthreads + 127) / 128, 128>>>(
        x, tix, W1, b1, W2, b2, out);
}